// round 9
// baseline (speedup 1.0000x reference)
#include <cuda_runtime.h>
#include <cuda_bf16.h>
#include <cstdint>

#define BB 256   // batch
#define TT 512   // encoder steps
#define FF 64    // input features
#define HH 1024  // hidden
#define TLEN 64  // decoder steps
#define N3 3072  // 3*H output columns (gate-interleaved)
#define NCT 48   // tensor chunks (aug K 3072 / 64)
#define NCF 16   // ffma chunks (K 1024 / 64)
#define NSTG_T 8 // tensor ring stages (power of 2)
#define NSTG_F 3 // ffma ring stages

#define NT 32                     // tensor columns per 96-tile
#define NF 64                     // ffma columns per 96-tile

#define AT_B 8192                 // tensor A tile: 64 rows x 128B (SW128)
#define BT_B 4096                 // tensor B tile: 32 rows x 128B
#define STG_T (AT_B + BT_B)       // 12288
#define AF_B 16384                // ffma A^T tile: [64k][64m] f32
#define BF_B 16384                // ffma B^T tile: [64k][64n] f32
#define STG_F (AF_B + BF_B)       // 32768
#define HDR 1024
#define OFF_T HDR                                  // 1024
#define OFF_F (HDR + NSTG_T * STG_T)               // 99328
#define SMEMSZ (OFF_F + NSTG_F * STG_F)            // 197632

__device__ __forceinline__ uint32_t sw128(uint32_t off) { return off ^ ((off >> 3) & 0x70); }

// ---------------- device scratch ----------------
__device__ __align__(128) __nv_bfloat16 g_Wt[2][32][NCT][NT * 64];   // 12.6 MB
__device__ __align__(128) float g_Wf[2][32][NCF][64][NF];            // 16.8 MB
__device__ __align__(128) __nv_bfloat16 g_ht[2][4][NCT][64 * 64];    // 3 MB
__device__ __align__(128) float g_hf[2][4][NCF][64][64];             // 4 MB
__device__ float g_bih_e[N3], g_bhh_e[N3], g_bih_d[N3], g_bhh_d[N3];
__device__ float g_Wihp_e[(size_t)HH * 192];
__device__ float g_Wih_d[N3];

// ---------------- PTX helpers ----------------
__device__ __forceinline__ void cp16(uint32_t smaddr, const void* g) {
    asm volatile("cp.async.cg.shared.global [%0], [%1], 16;" :: "r"(smaddr), "l"(g));
}
__device__ __forceinline__ void ldsm_x4(uint32_t* r, uint32_t addr) {
    asm volatile("ldmatrix.sync.aligned.m8n8.x4.shared.b16 {%0,%1,%2,%3}, [%4];"
                 : "=r"(r[0]), "=r"(r[1]), "=r"(r[2]), "=r"(r[3]) : "r"(addr));
}
__device__ __forceinline__ void mma_bf16(float* c, const uint32_t* a, uint32_t b0, uint32_t b1) {
    asm volatile("mma.sync.aligned.m16n8k16.row.col.f32.bf16.bf16.f32 "
                 "{%0,%1,%2,%3}, {%4,%5,%6,%7}, {%8,%9}, {%0,%1,%2,%3};"
                 : "+f"(c[0]), "+f"(c[1]), "+f"(c[2]), "+f"(c[3])
                 : "r"(a[0]), "r"(a[1]), "r"(a[2]), "r"(a[3]), "r"(b0), "r"(b1));
}
__device__ __forceinline__ void mbar_init(uint32_t mbar, uint32_t cnt) {
    asm volatile("mbarrier.init.shared.b64 [%0], %1;" :: "r"(mbar), "r"(cnt) : "memory");
}
__device__ __forceinline__ void mbar_arrive(uint32_t mbar) {
    asm volatile("mbarrier.arrive.shared.b64 _, [%0];" :: "r"(mbar) : "memory");
}
__device__ __forceinline__ void mbar_expect_tx(uint32_t mbar, uint32_t bytes) {
    asm volatile("mbarrier.arrive.expect_tx.shared.b64 _, [%0], %1;"
                 :: "r"(mbar), "r"(bytes) : "memory");
}
__device__ __forceinline__ void mbar_wait(uint32_t mbar, uint32_t parity) {
    asm volatile(
        "{\n\t.reg .pred P1;\n\t"
        "WL_%=:\n\t"
        "mbarrier.try_wait.parity.acquire.cta.shared::cta.b64 P1, [%0], %1, 0x989680;\n\t"
        "@P1 bra.uni WD_%=;\n\t"
        "bra.uni WL_%=;\n\t"
        "WD_%=:\n\t}"
        :: "r"(mbar), "r"(parity) : "memory");
}
__device__ __forceinline__ void bulk_g2s(uint32_t dst, const void* src, uint32_t bytes, uint32_t mbar) {
    asm volatile("cp.async.bulk.shared::cluster.global.mbarrier::complete_tx::bytes "
                 "[%0], [%1], %2, [%3];"
                 :: "r"(dst), "l"(src), "r"(bytes), "r"(mbar) : "memory");
}
__device__ __forceinline__ void ffma2(uint64_t& d, uint64_t a, uint64_t b) {
    asm volatile("fma.rn.f32x2 %0, %1, %2, %0;" : "+l"(d) : "l"(a), "l"(b));
}
__device__ __forceinline__ void upk(uint64_t d, float& x, float& y) {
    asm("mov.b64 {%0,%1}, %2;" : "=f"(x), "=f"(y) : "l"(d));
}
__device__ __forceinline__ void lds_v2u64(uint64_t& a, uint64_t& b, uint32_t addr) {
    asm volatile("ld.shared.v2.u64 {%0,%1}, [%2];" : "=l"(a), "=l"(b) : "r"(addr));
}
__device__ __forceinline__ void lds_v2f32(float& a, float& b, uint32_t addr) {
    asm volatile("ld.shared.v2.f32 {%0,%1}, [%2];" : "=f"(a), "=f"(b) : "r"(addr));
}
__device__ __forceinline__ uint64_t dup(float x) {
    uint64_t d; asm("mov.b64 %0, {%1,%1};" : "=l"(d) : "f"(x)); return d;
}

// ---------------- prep: tensor aug weights (cols 0..31 of each 96-tile) ----------------
__global__ void prep_wt(const float* __restrict__ encW, const float* __restrict__ decW) {
    size_t idx = (size_t)blockIdx.x * blockDim.x + threadIdx.x;
    const size_t one = (size_t)1024 * 3072;
    if (idx >= 2 * one) return;
    int which = idx >= one;
    size_t rem = which ? idx - one : idx;
    int jt = (int)(rem / 3072);     // 0..1023
    int k  = (int)(rem % 3072);     // aug k
    int nb = jt / NT, jr = jt % NT;
    int u = nb * 32 + jr / 3, g = jr % 3;
    const float* W = which ? decW : encW;
    float w = W[(size_t)(g * HH + u) * HH + (k & 1023)];
    __nv_bfloat16 hi = __float2bfloat16(w);
    __nv_bfloat16 out = (k < 2048) ? hi : __float2bfloat16(w - __bfloat162float(hi));
    uint32_t swb = sw128((uint32_t)(jr * 128 + (k & 63) * 2));
    g_Wt[which][nb][k >> 6][swb >> 1] = out;
}

// ---------------- prep: ffma fp32 transposed weights (cols 32..95 of each tile) ----------------
__global__ void prep_wf(const float* __restrict__ encW, const float* __restrict__ decW) {
    size_t idx = (size_t)blockIdx.x * blockDim.x + threadIdx.x;
    const size_t one = (size_t)2048 * 1024;
    if (idx >= 2 * one) return;
    int which = idx >= one;
    size_t rem = which ? idx - one : idx;
    int jf = (int)(rem / 1024);     // 0..2047
    int k  = (int)(rem % 1024);
    int nb = jf / NF, n = jf % NF;
    int jc = NT + n;                // column within 96-tile
    int u = nb * 32 + jc / 3, g = jc % 3;
    const float* W = which ? decW : encW;
    g_Wf[which][nb][k >> 6][k & 63][n] = W[(size_t)(g * HH + u) * HH + k];
}

// ---------------- prep: biases, W_ih, zero h, init d_out ----------------
__global__ void prep_misc(const float* __restrict__ ebih, const float* __restrict__ ebhh,
                          const float* __restrict__ dbih, const float* __restrict__ dbhh,
                          const float* __restrict__ eWih, const float* __restrict__ dWih,
                          const float* __restrict__ fcb, float* __restrict__ dout) {
    int tid = blockIdx.x * blockDim.x + threadIdx.x;
    int stride = gridDim.x * blockDim.x;
    for (int i = tid; i < N3; i += stride) {
        int u = i / 3, g = i - 3 * u;
        int o = g * HH + u;
        g_bih_e[i] = ebih[o];
        g_bhh_e[i] = ebhh[o];
        g_bih_d[i] = dbih[o];
        g_bhh_d[i] = dbhh[o];
        g_Wih_d[i] = dWih[o];
    }
    for (int i = tid; i < HH * 192; i += stride) {
        int u = i / 192, rem = i - u * 192;
        int g = rem >> 6, f = rem & 63;
        g_Wihp_e[i] = eWih[(size_t)(g * HH + u) * FF + f];
    }
    const int nt = 2 * 4 * NCT * 4096 / 2;
    for (int i = tid; i < nt; i += stride) ((uint32_t*)g_ht)[i] = 0u;
    const int nf = 2 * 4 * NCF * 4096;
    for (int i = tid; i < nf; i += stride) ((float*)g_hf)[i] = 0.f;
    for (int i = tid; i < BB * TLEN; i += stride) dout[i] = fcb[0];
}

// ---------------- step kernel: 4 tensor warps + 8 ffma warps (384 threads) ----------------
// grid (32, 4): nb = 96-col tile (32 tensor + 64 ffma), mb = 64-row batch tile.
__global__ __launch_bounds__(384) void gru_step_kernel(
    int t, int mode, int par,
    const float* __restrict__ x, const float* __restrict__ fcW, float* __restrict__ dout)
{
    const float* __restrict__ bih = mode ? g_bih_d : g_bih_e;
    const float* __restrict__ bhh = mode ? g_bhh_d : g_bhh_e;

    extern __shared__ __align__(16) unsigned char smem_raw[];
    const int tid = threadIdx.x;
    const int lane = tid & 31, warp = tid >> 5;
    const int nb = blockIdx.x, mb = blockIdx.y;

    const uint32_t smB = (uint32_t)__cvta_generic_to_shared(smem_raw);
    const uint32_t fullT = smB, emptyT = smB + 64;

    const __nv_bfloat16* __restrict__ At = &g_ht[par][mb][0][0];
    const __nv_bfloat16* __restrict__ Bt = &g_Wt[mode][nb][0][0];
    const float* __restrict__ Af = &g_hf[par][mb][0][0][0];
    const float* __restrict__ Bf = &g_Wf[mode][nb][0][0][0];

    if (tid == 0) {
        #pragma unroll
        for (int s = 0; s < NSTG_T; s++) { mbar_init(fullT + 8 * s, 1); mbar_init(emptyT + 8 * s, 4); }
    }
    __syncthreads();

    float* Csm = (float*)(smem_raw + HDR);               // 64 x 96, pitch 99 (post-loop)
    float* Xs  = (float*)(smem_raw + HDR + 25600);

    if (warp < 4) {
        // ================= tensor warps: cols 0..31, aug K=3072 (bulk-TMA ring) =================
        auto issue_t = [&](int c) {
            const int s = c & (NSTG_T - 1);
            const uint32_t m_ = fullT + 8 * s;
            mbar_expect_tx(m_, STG_T);
            const uint32_t d = smB + OFF_T + s * STG_T;
            bulk_g2s(d,        At + (size_t)c * 4096, AT_B, m_);
            bulk_g2s(d + AT_B, Bt + (size_t)c * 2048, BT_B, m_);
        };
        if (tid == 0) {
            #pragma unroll
            for (int s = 0; s < NSTG_T - 1; s++) issue_t(s);
        }

        const int wm = warp >> 1, wn = warp & 1;         // 2x2 warps, 32x16 tiles
        float acc[2][2][4];
        #pragma unroll
        for (int mi = 0; mi < 2; mi++)
            #pragma unroll
            for (int ni = 0; ni < 2; ni++)
                #pragma unroll
                for (int q = 0; q < 4; q++) acc[mi][ni][q] = 0.f;

        for (int c = 0; c < NCT; c++) {
            if (tid == 0) {
                int cn = c + NSTG_T - 1;
                if (cn < NCT) {
                    int r = cn >> 3;
                    if (r >= 1) mbar_wait(emptyT + 8 * (cn & (NSTG_T - 1)), (r - 1) & 1);
                    issue_t(cn);
                }
            }
            mbar_wait(fullT + 8 * (c & (NSTG_T - 1)), (c >> 3) & 1);
            const uint32_t sA = smB + OFF_T + (c & (NSTG_T - 1)) * STG_T;
            const uint32_t sB2 = sA + AT_B;
            #pragma unroll
            for (int ks = 0; ks < 4; ks++) {
                uint32_t ra[2][4], rb[4];
                #pragma unroll
                for (int mi = 0; mi < 2; mi++) {
                    uint32_t off = (uint32_t)((wm * 32 + mi * 16 + (lane & 15)) * 128
                                              + ks * 32 + (lane >> 4) * 16);
                    ldsm_x4(ra[mi], sA + sw128(off));
                }
                {   // B n16k16 via x4: rows wn*16 + (lane&15), halves (lane>>4)
                    uint32_t off = (uint32_t)((wn * 16 + (lane & 15)) * 128
                                              + ks * 32 + (lane >> 4) * 16);
                    ldsm_x4(rb, sB2 + sw128(off));
                }
                // x4 B reg order: {n0-7 k0-7, n8-15 k0-7, n0-7 k8-15, n8-15 k8-15}
                #pragma unroll
                for (int mi = 0; mi < 2; mi++) {
                    mma_bf16(acc[mi][0], ra[mi], rb[0], rb[2]);
                    mma_bf16(acc[mi][1], ra[mi], rb[1], rb[3]);
                }
            }
            if (lane == 0) mbar_arrive(emptyT + 8 * (c & (NSTG_T - 1)));
        }
        __syncthreads();
        #pragma unroll
        for (int mi = 0; mi < 2; mi++)
            #pragma unroll
            for (int ni = 0; ni < 2; ni++) {
                int m = wm * 32 + mi * 16 + (lane >> 2);
                int n = wn * 16 + ni * 8 + ((lane & 3) << 1);
                Csm[m * 99 + n]           = acc[mi][ni][0];
                Csm[m * 99 + n + 1]       = acc[mi][ni][1];
                Csm[(m + 8) * 99 + n]     = acc[mi][ni][2];
                Csm[(m + 8) * 99 + n + 1] = acc[mi][ni][3];
            }
    } else {
        // ====== ffma warps (8): cols 32..95, exact fp32 K=1024, cp.async + named-barrier ring ======
        const int tf = tid - 128;                        // 0..255
        const int mg = tf >> 3;                          // 0..31 -> rows 2*mg, 2*mg+1
        const int ng = tf & 7;                           // 0..7  -> cols ng*8 .. +7 (within ffma block)

        auto issue_f = [&](int c) {
            const uint32_t d = smB + OFF_F + (c % NSTG_F) * STG_F;
            const float* srcA = Af + (size_t)c * 4096;
            const float* srcB = Bf + (size_t)c * 4096;
            #pragma unroll
            for (int q = 0; q < 4; q++) {               // A: 16384B = 256 thr x 4 x 16B
                int idx = tf + q * 256;
                cp16(d + idx * 16, srcA + idx * 4);
            }
            #pragma unroll
            for (int q = 0; q < 4; q++) {               // B: 16384B
                int idx = tf + q * 256;
                cp16(d + AF_B + idx * 16, srcB + idx * 4);
            }
        };

        issue_f(0); asm volatile("cp.async.commit_group;" ::: "memory");
        issue_f(1); asm volatile("cp.async.commit_group;" ::: "memory");

        uint64_t acc2[2][4];
        #pragma unroll
        for (int m = 0; m < 2; m++)
            #pragma unroll
            for (int p = 0; p < 4; p++) acc2[m][p] = 0ull;

        for (int c = 0; c < NCF; c++) {
            asm volatile("cp.async.wait_group 1;" ::: "memory");
            asm volatile("bar.sync 1, 256;" ::: "memory");
            if (c + 2 < NCF) issue_f(c + 2);
            asm volatile("cp.async.commit_group;" ::: "memory");

            const uint32_t sA = smB + OFF_F + (c % NSTG_F) * STG_F;
            const uint32_t sB2 = sA + AF_B;
            #pragma unroll 4
            for (int k = 0; k < 64; k++) {
                float a0, a1;
                lds_v2f32(a0, a1, sA + (uint32_t)(k * 256 + mg * 8));
                uint64_t B0, B1, B2, B3;
                lds_v2u64(B0, B1, sB2 + (uint32_t)(k * 256 + ng * 32));
                lds_v2u64(B2, B3, sB2 + (uint32_t)(k * 256 + ng * 32 + 16));
                uint64_t A0 = dup(a0), A1 = dup(a1);
                ffma2(acc2[0][0], B0, A0); ffma2(acc2[0][1], B1, A0);
                ffma2(acc2[0][2], B2, A0); ffma2(acc2[0][3], B3, A0);
                ffma2(acc2[1][0], B0, A1); ffma2(acc2[1][1], B1, A1);
                ffma2(acc2[1][2], B2, A1); ffma2(acc2[1][3], B3, A1);
            }
        }
        __syncthreads();
        #pragma unroll
        for (int m = 0; m < 2; m++)
            #pragma unroll
            for (int p = 0; p < 4; p++) {
                float lo, hi;
                upk(acc2[m][p], lo, hi);
                Csm[(2 * mg + m) * 99 + NT + ng * 8 + 2 * p]     = lo;
                Csm[(2 * mg + m) * 99 + NT + ng * 8 + 2 * p + 1] = hi;
            }
    }

    if (mode == 0) {
        for (int id = tid; id < 1024; id += 384) {
            int r = id >> 4, c4 = id & 15;
            ((float4*)Xs)[r * 16 + c4] =
                *(const float4*)(x + ((size_t)(mb * 64 + r) * TT + t) * FF + c4 * 4);
        }
    }
    __syncthreads();

    // ---- fused GRU epilogue (first 256 threads): thread owns (row bl, 8 units) ----
    if (tid < 256) {
        const int bl = tid >> 2, uq = tid & 3;
        const int b = mb * 64 + bl;
        float inp = 0.f;
        if (mode && t > 0) inp = dout[b * TLEN + (t - 1)];
        float fcsum = 0.f;
        const float4* xs4 = (const float4*)(Xs + bl * 64);
        __nv_bfloat16* __restrict__ htd = &g_ht[par ^ 1][mb][0][0];
        float* __restrict__ hfd = &g_hf[par ^ 1][mb][0][0][0];
        const float* __restrict__ hfs = &g_hf[par][mb][0][0][0];

        #pragma unroll
        for (int i = 0; i < 8; i++) {
            int ul = uq * 8 + i;
            int u = nb * 32 + ul;
            float ar = Csm[bl * 99 + ul * 3 + 0];
            float az = Csm[bl * 99 + ul * 3 + 1];
            float an = Csm[bl * 99 + ul * 3 + 2];
            float gr, gz, gn;
            if (mode == 0) {
                gr = gz = gn = 0.f;
                const float4* wr4 = (const float4*)(g_Wihp_e + (size_t)u * 192);
                #pragma unroll
                for (int q = 0; q < 16; q++) {
                    float4 xv = xs4[q];
                    float4 a = wr4[q], bq = wr4[16 + q], cq = wr4[32 + q];
                    gr += xv.x * a.x + xv.y * a.y + xv.z * a.z + xv.w * a.w;
                    gz += xv.x * bq.x + xv.y * bq.y + xv.z * bq.z + xv.w * bq.w;
                    gn += xv.x * cq.x + xv.y * cq.y + xv.z * cq.z + xv.w * cq.w;
                }
            } else {
                gr = inp * g_Wih_d[u * 3 + 0];
                gz = inp * g_Wih_d[u * 3 + 1];
                gn = inp * g_Wih_d[u * 3 + 2];
            }
            float hprev = hfs[(size_t)(u >> 6) * 4096 + (u & 63) * 64 + bl];
            float rg = 1.f / (1.f + __expf(-(gr + bih[u * 3 + 0] + ar + bhh[u * 3 + 0])));
            float zg = 1.f / (1.f + __expf(-(gz + bih[u * 3 + 1] + az + bhh[u * 3 + 1])));
            float ng = tanhf(gn + bih[u * 3 + 2] + rg * (an + bhh[u * 3 + 2]));
            float hn = (1.f - zg) * ng + zg * hprev;
            __nv_bfloat16 hi = __float2bfloat16(hn);
            __nv_bfloat16 lo = __float2bfloat16(hn - __bfloat162float(hi));
            const uint32_t swo = sw128((uint32_t)(bl * 128 + (u & 63) * 2));
            *(__nv_bfloat16*)((char*)htd + (size_t)(u >> 6) * AT_B + swo)        = hi;
            *(__nv_bfloat16*)((char*)htd + (size_t)(32 + (u >> 6)) * AT_B + swo) = hi;
            *(__nv_bfloat16*)((char*)htd + (size_t)(16 + (u >> 6)) * AT_B + swo) = lo;
            hfd[(size_t)(u >> 6) * 4096 + (u & 63) * 64 + bl] = hn;
            if (mode) fcsum += hn * fcW[u];
        }
        if (mode) {
            fcsum += __shfl_down_sync(0xffffffffu, fcsum, 2, 4);
            fcsum += __shfl_down_sync(0xffffffffu, fcsum, 1, 4);
            if (uq == 0) atomicAdd(&dout[b * TLEN + t], fcsum);
        }
    }
}

// ---------------- host launch ----------------
extern "C" void kernel_launch(void* const* d_in, const int* in_sizes, int n_in,
                              void* d_out, int out_size) {
    const float* x    = (const float*)d_in[0];
    const float* eWih = (const float*)d_in[1];
    const float* eWhh = (const float*)d_in[2];
    const float* ebih = (const float*)d_in[3];
    const float* ebhh = (const float*)d_in[4];
    const float* dWih = (const float*)d_in[5];
    const float* dWhh = (const float*)d_in[6];
    const float* dbih = (const float*)d_in[7];
    const float* dbhh = (const float*)d_in[8];
    const float* fcW  = (const float*)d_in[9];
    const float* fcb  = (const float*)d_in[10];
    float* out = (float*)d_out;

    cudaFuncSetAttribute(gru_step_kernel,
                         cudaFuncAttributeMaxDynamicSharedMemorySize, SMEMSZ);

    prep_wt<<<(unsigned)((2 * (size_t)1024 * 3072 + 255) / 256), 256>>>(eWhh, dWhh);
    prep_wf<<<(unsigned)((2 * (size_t)2048 * 1024 + 255) / 256), 256>>>(eWhh, dWhh);
    prep_misc<<<1024, 256>>>(ebih, ebhh, dbih, dbhh, eWih, dWih, fcb, out);

    dim3 grid(N3 / 96, BB / 64);   // (32, 4)
    for (int t = 0; t < TT; t++)
        gru_step_kernel<<<grid, 384, SMEMSZ>>>(t, 0, t & 1, x, fcW, out);
    for (int s = 0; s < TLEN; s++)
        gru_step_kernel<<<grid, 384, SMEMSZ>>>(s, 1, s & 1, x, fcW, out);
}

// round 10
// speedup vs baseline: 2.5767x; 2.5767x over previous
#include <cuda_runtime.h>
#include <cuda_bf16.h>
#include <cstdint>

#define BB 256   // batch
#define TT 512   // encoder steps
#define FF 64    // input features
#define HH 1024  // hidden
#define TLEN 64  // decoder steps
#define N3 3072  // 3*H output columns (gate-interleaved)
#define NC 24    // chunk passes: 8 main (A*Wa) + 8 cross (B*Wa) + 8 cross (A*Wb)
#define NSTG 8   // ring stages

#define A_TILE_B 8192           // h tile: 64 rows x 128 k-bytes (SW128)
#define B_TILE_B 12288          // W tile: 96 rows x 128 k-bytes
#define STAGE_B  (A_TILE_B + B_TILE_B)   // 20480
#define HDR 1024
#define SMEMSZ (HDR + NSTG * STAGE_B)    // 164864

__device__ __forceinline__ uint32_t sw128(uint32_t off) { return off ^ ((off >> 3) & 0x70); }

// ---------------- device scratch (static globals) ----------------
// W limbs as swizzled tiles: chunks 0-7 = Wa (scale 2^-11), 8-15 = Wb (scale 2^-18)
__device__ __align__(128) int8_t g_Wq[2][32][16][96 * 128];          // 12.6 MB
// h limbs: chunks 0-7 = A (scale 2^-7), 8-15 = B (scale 2^-14)
__device__ __align__(128) int8_t g_hq[2][4][16][64 * 128];           // 1 MB
__device__ float g_hf[2][4][64][HH];                                 // exact h, 2 MB
__device__ float g_bih_e[N3], g_bhh_e[N3], g_bih_d[N3], g_bhh_d[N3];
__device__ float g_Wihp_e[(size_t)HH * 192];   // enc W_ih per-unit [r|z|n]
__device__ float g_Wih_d[N3];                  // dec W_ih permuted

// ---------------- PTX helpers ----------------
__device__ __forceinline__ void ldsm_x4(uint32_t* r, uint32_t addr) {
    asm volatile("ldmatrix.sync.aligned.m8n8.x4.shared.b16 {%0,%1,%2,%3}, [%4];"
                 : "=r"(r[0]), "=r"(r[1]), "=r"(r[2]), "=r"(r[3]) : "r"(addr));
}
__device__ __forceinline__ void ldsm_x2(uint32_t* r, uint32_t addr) {
    asm volatile("ldmatrix.sync.aligned.m8n8.x2.shared.b16 {%0,%1}, [%2];"
                 : "=r"(r[0]), "=r"(r[1]) : "r"(addr));
}
__device__ __forceinline__ void mma_s8(int* c, const uint32_t* a, uint32_t b0, uint32_t b1) {
    asm volatile("mma.sync.aligned.m16n8k32.row.col.s32.s8.s8.s32 "
                 "{%0,%1,%2,%3}, {%4,%5,%6,%7}, {%8,%9}, {%0,%1,%2,%3};"
                 : "+r"(c[0]), "+r"(c[1]), "+r"(c[2]), "+r"(c[3])
                 : "r"(a[0]), "r"(a[1]), "r"(a[2]), "r"(a[3]), "r"(b0), "r"(b1));
}
__device__ __forceinline__ void mbar_init(uint32_t mbar, uint32_t cnt) {
    asm volatile("mbarrier.init.shared.b64 [%0], %1;" :: "r"(mbar), "r"(cnt) : "memory");
}
__device__ __forceinline__ void mbar_expect_tx(uint32_t mbar, uint32_t bytes) {
    asm volatile("mbarrier.arrive.expect_tx.shared.b64 _, [%0], %1;"
                 :: "r"(mbar), "r"(bytes) : "memory");
}
__device__ __forceinline__ void mbar_wait(uint32_t mbar, uint32_t parity) {
    asm volatile(
        "{\n\t.reg .pred P1;\n\t"
        "WL_%=:\n\t"
        "mbarrier.try_wait.parity.acquire.cta.shared::cta.b64 P1, [%0], %1, 0x989680;\n\t"
        "@P1 bra.uni WD_%=;\n\t"
        "bra.uni WL_%=;\n\t"
        "WD_%=:\n\t}"
        :: "r"(mbar), "r"(parity) : "memory");
}
__device__ __forceinline__ void bulk_g2s(uint32_t dst, const void* src, uint32_t bytes, uint32_t mbar) {
    asm volatile("cp.async.bulk.shared::cluster.global.mbarrier::complete_tx::bytes "
                 "[%0], [%1], %2, [%3];"
                 :: "r"(dst), "l"(src), "r"(bytes), "r"(mbar) : "memory");
}

// ---------------- prep: W int8 limbs, swizzled tiles ----------------
// permuted col j = 3u+g; tile nb = j/96, row jr = j%96. W = Wa/2^11 + Wb/2^18.
__global__ void prep_wq(const float* __restrict__ encW, const float* __restrict__ decW) {
    size_t idx = (size_t)blockIdx.x * blockDim.x + threadIdx.x;
    const size_t one = (size_t)N3 * HH;
    if (idx >= 2 * one) return;
    int which = idx >= one;
    size_t rem = which ? idx - one : idx;
    int j = (int)(rem / HH), k = (int)(rem % HH);
    int u = j / 3, g = j % 3;
    int nb = j / 96, jr = j % 96;
    const float* W = which ? decW : encW;
    float w = W[(size_t)(g * HH + u) * HH + k];
    int ia = __float2int_rn(w * 2048.f);
    ia = max(-127, min(127, ia));
    float resid = w - (float)ia * (1.f / 2048.f);
    int ib = __float2int_rn(resid * 262144.f);
    ib = max(-127, min(127, ib));
    uint32_t sw = sw128((uint32_t)(jr * 128 + (k & 127)));
    g_Wq[which][nb][k >> 7][sw]     = (int8_t)ia;
    g_Wq[which][nb][8 + (k >> 7)][sw] = (int8_t)ib;
}

// ---------------- prep: biases, W_ih, zero h, init d_out ----------------
__global__ void prep_misc(const float* __restrict__ ebih, const float* __restrict__ ebhh,
                          const float* __restrict__ dbih, const float* __restrict__ dbhh,
                          const float* __restrict__ eWih, const float* __restrict__ dWih,
                          const float* __restrict__ fcb, float* __restrict__ dout) {
    int tid = blockIdx.x * blockDim.x + threadIdx.x;
    int stride = gridDim.x * blockDim.x;
    for (int i = tid; i < N3; i += stride) {
        int u = i / 3, g = i - 3 * u;
        int o = g * HH + u;
        g_bih_e[i] = ebih[o];
        g_bhh_e[i] = ebhh[o];
        g_bih_d[i] = dbih[o];
        g_bhh_d[i] = dbhh[o];
        g_Wih_d[i] = dWih[o];
    }
    for (int i = tid; i < HH * 192; i += stride) {
        int u = i / 192, rem = i - u * 192;
        int g = rem >> 6, f = rem & 63;
        g_Wihp_e[i] = eWih[(size_t)(g * HH + u) * FF + f];
    }
    const int nq = (int)(sizeof(g_hq) / 4);
    for (int i = tid; i < nq; i += stride) ((uint32_t*)g_hq)[i] = 0u;
    const int nf = (int)(sizeof(g_hf) / 4);
    for (int i = tid; i < nf; i += stride) ((float*)g_hf)[i] = 0.f;
    for (int i = tid; i < BB * TLEN; i += stride) dout[i] = fcb[0];
}

// ---------------- one recurrent step: IMMA limb GEMM + fused GRU epilogue ----------------
// grid (32, 4): blockIdx.x = 96-col tile, blockIdx.y = 64-row batch tile. 256 threads.
__global__ __launch_bounds__(256) void gru_step_kernel(
    int t, int mode, int par,
    const float* __restrict__ x, const float* __restrict__ fcW, float* __restrict__ dout)
{
    const float* __restrict__ bih = mode ? g_bih_d : g_bih_e;
    const float* __restrict__ bhh = mode ? g_bhh_d : g_bhh_e;

    extern __shared__ __align__(16) unsigned char smem_raw[];
    const int tid = threadIdx.x;
    const int lane = tid & 31, warp = tid >> 5;
    const int wm = warp >> 2, wn = warp & 3;     // 2 x 4 warps -> 32x24 warp tiles
    const int nb = blockIdx.x, mb = blockIdx.y;

    const uint32_t smB = (uint32_t)__cvta_generic_to_shared(smem_raw);
    const uint32_t fullB = smB;                  // 8 mbarriers x 8B
    const uint32_t smData = smB + HDR;

    const int8_t* __restrict__ Hq = &g_hq[par][mb][0][0];
    const int8_t* __restrict__ Wq = &g_Wq[mode][nb][0][0];

    if (tid == 0) {
        #pragma unroll
        for (int s = 0; s < NSTG; s++) mbar_init(fullB + 8 * s, 1);
    }
    __syncthreads();

    // chunk schedule: c<8: A*Wa (main); 8<=c<16: B*Wa (cross); 16<=c<24: A*Wb (cross)
    auto issue = [&](int c) {
        const int s = c & (NSTG - 1);
        const uint32_t m_ = fullB + 8 * s;
        mbar_expect_tx(m_, STAGE_B);
        const uint32_t d = smData + s * STAGE_B;
        const int hc = (c < 16) ? c : c - 16;
        const int wc = (c < 8) ? c : c - 8;
        bulk_g2s(d,            Hq + (size_t)hc * 8192,  A_TILE_B, m_);
        bulk_g2s(d + A_TILE_B, Wq + (size_t)wc * 12288, B_TILE_B, m_);
    };

    if (tid == 0) {
        #pragma unroll
        for (int s = 0; s < NSTG - 1; s++) issue(s);
    }

    int acc_m[2][3][4], acc_x[2][3][4];
    #pragma unroll
    for (int mi = 0; mi < 2; mi++)
        #pragma unroll
        for (int ni = 0; ni < 3; ni++)
            #pragma unroll
            for (int q = 0; q < 4; q++) { acc_m[mi][ni][q] = 0; acc_x[mi][ni][q] = 0; }

    // per-chunk compute: identical addressing to proven bf16 path (byte-compatible frags)
    auto do_chunk = [&](int c, int (*acc)[3][4]) {
        __syncthreads();                          // slot (c-1)%8 drained by all warps
        if (tid == 0 && c + NSTG - 1 < NC) issue(c + NSTG - 1);
        mbar_wait(fullB + 8 * (c & (NSTG - 1)), (c >> 3) & 1);
        const uint32_t sA = smData + (c & (NSTG - 1)) * STAGE_B;
        const uint32_t sB = sA + A_TILE_B;
        #pragma unroll
        for (int ks = 0; ks < 4; ks++) {          // 4 x k32 int8 per chunk (128 k-bytes)
            uint32_t ra[2][4], rb[3][2];
            #pragma unroll
            for (int mi = 0; mi < 2; mi++) {
                uint32_t off = (uint32_t)((wm * 32 + mi * 16 + (lane & 15)) * 128
                                          + ks * 32 + (lane >> 4) * 16);
                ldsm_x4(ra[mi], sA + sw128(off));
            }
            #pragma unroll
            for (int ni = 0; ni < 3; ni++) {
                uint32_t off = (uint32_t)((wn * 24 + ni * 8 + (lane & 7)) * 128
                                          + ks * 32 + ((lane >> 3) & 1) * 16);
                ldsm_x2(rb[ni], sB + sw128(off));
            }
            #pragma unroll
            for (int mi = 0; mi < 2; mi++)
                #pragma unroll
                for (int ni = 0; ni < 3; ni++)
                    mma_s8(acc[mi][ni], ra[mi], rb[ni][0], rb[ni][1]);
        }
    };

    for (int c = 0; c < 8; c++)  do_chunk(c, acc_m);
    for (int c = 8; c < NC; c++) do_chunk(c, acc_x);

    // ---- combine limbs, stage to smem ----
    __syncthreads();
    float* Csm = (float*)(smem_raw + HDR);               // 64 x 96, pitch 99
    float* Xs  = (float*)(smem_raw + HDR + 25600);       // 64 x 64 floats
    #pragma unroll
    for (int mi = 0; mi < 2; mi++)
        #pragma unroll
        for (int ni = 0; ni < 3; ni++) {
            int m = wm * 32 + mi * 16 + (lane >> 2);
            int n = wn * 24 + ni * 8 + ((lane & 3) << 1);
            #pragma unroll
            for (int q = 0; q < 4; q++) {
                float v = ((float)acc_m[mi][ni][q]
                           + (float)acc_x[mi][ni][q] * 0.0078125f) * 3.8146973e-6f;
                int mm = m + (q >> 1) * 8;
                int nn = n + (q & 1);
                Csm[mm * 99 + nn] = v;
            }
        }
    if (mode == 0) {
        #pragma unroll
        for (int q = 0; q < 4; q++) {
            int id = tid + q * 256;
            int r = id >> 4, c4 = id & 15;
            ((float4*)Xs)[r * 16 + c4] =
                *(const float4*)(x + ((size_t)(mb * 64 + r) * TT + t) * FF + c4 * 4);
        }
    }
    __syncthreads();

    // ---- fused GRU epilogue: thread owns (batch row bl, 8 hidden units) ----
    const int bl = tid >> 2, uq = tid & 3;
    const int b = mb * 64 + bl;
    float inp = 0.f;
    if (mode && t > 0) inp = dout[b * TLEN + (t - 1)];
    float fcsum = 0.f;
    const float4* xs4 = (const float4*)(Xs + bl * 64);
    int8_t* __restrict__ hqd = &g_hq[par ^ 1][mb][0][0];
    float* __restrict__ hfd = &g_hf[par ^ 1][mb][0][0];
    const float* __restrict__ hfs = &g_hf[par][mb][0][0];

    #pragma unroll
    for (int i = 0; i < 8; i++) {
        int ul = uq * 8 + i;
        int u = nb * 32 + ul;
        float ar = Csm[bl * 99 + ul * 3 + 0];
        float az = Csm[bl * 99 + ul * 3 + 1];
        float an = Csm[bl * 99 + ul * 3 + 2];
        float gr, gz, gn;
        if (mode == 0) {
            gr = gz = gn = 0.f;
            const float4* wr4 = (const float4*)(g_Wihp_e + (size_t)u * 192);
            #pragma unroll
            for (int q = 0; q < 16; q++) {
                float4 xv = xs4[q];
                float4 a = wr4[q], bq = wr4[16 + q], cq = wr4[32 + q];
                gr += xv.x * a.x + xv.y * a.y + xv.z * a.z + xv.w * a.w;
                gz += xv.x * bq.x + xv.y * bq.y + xv.z * bq.z + xv.w * bq.w;
                gn += xv.x * cq.x + xv.y * cq.y + xv.z * cq.z + xv.w * cq.w;
            }
        } else {
            gr = inp * g_Wih_d[u * 3 + 0];
            gz = inp * g_Wih_d[u * 3 + 1];
            gn = inp * g_Wih_d[u * 3 + 2];
        }
        float hprev = hfs[(size_t)bl * HH + u];
        float rg = 1.f / (1.f + __expf(-(gr + bih[u * 3 + 0] + ar + bhh[u * 3 + 0])));
        float zg = 1.f / (1.f + __expf(-(gz + bih[u * 3 + 1] + az + bhh[u * 3 + 1])));
        float ng = tanhf(gn + bih[u * 3 + 2] + rg * (an + bhh[u * 3 + 2]));
        float hn = (1.f - zg) * ng + zg * hprev;
        // int8 limbs: h ~ A/2^7 + B/2^14  (|h| < 1 guaranteed by GRU form)
        int A = __float2int_rn(hn * 128.f);
        A = max(-127, min(127, A));
        float resid = hn - (float)A * 0.0078125f;
        int Bq = __float2int_rn(resid * 16384.f);
        Bq = max(-127, min(127, Bq));
        const uint32_t swo = sw128((uint32_t)(bl * 128 + (u & 127)));
        hqd[(size_t)(u >> 7) * 8192 + swo]       = (int8_t)A;
        hqd[(size_t)(8 + (u >> 7)) * 8192 + swo] = (int8_t)Bq;
        hfd[(size_t)bl * HH + u] = hn;
        if (mode) fcsum += hn * fcW[u];
    }
    if (mode) {
        fcsum += __shfl_down_sync(0xffffffffu, fcsum, 2, 4);
        fcsum += __shfl_down_sync(0xffffffffu, fcsum, 1, 4);
        if (uq == 0) atomicAdd(&dout[b * TLEN + t], fcsum);
    }
}

// ---------------- host launch ----------------
extern "C" void kernel_launch(void* const* d_in, const int* in_sizes, int n_in,
                              void* d_out, int out_size) {
    const float* x    = (const float*)d_in[0];
    const float* eWih = (const float*)d_in[1];
    const float* eWhh = (const float*)d_in[2];
    const float* ebih = (const float*)d_in[3];
    const float* ebhh = (const float*)d_in[4];
    const float* dWih = (const float*)d_in[5];
    const float* dWhh = (const float*)d_in[6];
    const float* dbih = (const float*)d_in[7];
    const float* dbhh = (const float*)d_in[8];
    const float* fcW  = (const float*)d_in[9];
    const float* fcb  = (const float*)d_in[10];
    float* out = (float*)d_out;

    cudaFuncSetAttribute(gru_step_kernel,
                         cudaFuncAttributeMaxDynamicSharedMemorySize, SMEMSZ);

    prep_wq<<<(unsigned)((2 * (size_t)N3 * HH + 255) / 256), 256>>>(eWhh, dWhh);
    prep_misc<<<1024, 256>>>(ebih, ebhh, dbih, dbhh, eWih, dWih, fcb, out);

    dim3 grid(N3 / 96, BB / 64);   // (32, 4)
    for (int t = 0; t < TT; t++)
        gru_step_kernel<<<grid, 256, SMEMSZ>>>(t, 0, t & 1, x, fcW, out);
    for (int s = 0; s < TLEN; s++)
        gru_step_kernel<<<grid, 256, SMEMSZ>>>(s, 1, s & 1, x, fcW, out);
}

// round 11
// speedup vs baseline: 3.3384x; 1.2956x over previous
#include <cuda_runtime.h>
#include <cuda_bf16.h>
#include <cstdint>

#define BB 256   // batch
#define TT 512   // encoder steps
#define FF 64    // input features
#define HH 1024  // hidden
#define TLEN 64  // decoder steps
#define N3 3072  // 3*H output columns (gate-interleaved)
#define KK 3072  // augmented K: [h_hi | h_lo | h_hi]
#define NC 48    // K chunks of 64
#define NSTG 8   // pipeline stages

#define A_TILE_B 8192           // 64 rows x 128B
#define B_TILE_B 12288          // 96 rows x 128B
#define STAGE_B  (A_TILE_B + B_TILE_B)   // 20480
#define HDR 1024
#define SMEMSZ (HDR + NSTG * STAGE_B)    // 164864

__device__ __forceinline__ uint32_t sw128(uint32_t off) { return off ^ ((off >> 3) & 0x70); }

// ---------------- device scratch (static globals; no allocation) ----------------
// Weights as contiguous pre-swizzled tiles: [2][32 nb][48 c][96*64]
__device__ __align__(128) __nv_bfloat16 g_Wt[2][32][NC][96 * 64];
// h as contiguous pre-swizzled tiles: [2 par][4 mb][48 c][64*64]
__device__ __align__(128) __nv_bfloat16 g_ht[2][4][NC][64 * 64];
__device__ float g_bih_e[N3], g_bhh_e[N3], g_bih_d[N3], g_bhh_d[N3]; // permuted biases
__device__ float g_Wihp_e[(size_t)HH * 192];            // enc W_ih, per-unit [r|z|n]
__device__ float g_Wih_d[N3];                           // dec W_ih (scalar input), permuted

// ---------------- PTX helpers ----------------
__device__ __forceinline__ void ldsm_x4(uint32_t* r, uint32_t addr) {
    asm volatile("ldmatrix.sync.aligned.m8n8.x4.shared.b16 {%0,%1,%2,%3}, [%4];"
                 : "=r"(r[0]), "=r"(r[1]), "=r"(r[2]), "=r"(r[3]) : "r"(addr));
}
__device__ __forceinline__ void ldsm_x2(uint32_t* r, uint32_t addr) {
    asm volatile("ldmatrix.sync.aligned.m8n8.x2.shared.b16 {%0,%1}, [%2];"
                 : "=r"(r[0]), "=r"(r[1]) : "r"(addr));
}
__device__ __forceinline__ void mma_bf16(float* c, const uint32_t* a, uint32_t b0, uint32_t b1) {
    asm volatile("mma.sync.aligned.m16n8k16.row.col.f32.bf16.bf16.f32 "
                 "{%0,%1,%2,%3}, {%4,%5,%6,%7}, {%8,%9}, {%0,%1,%2,%3};"
                 : "+f"(c[0]), "+f"(c[1]), "+f"(c[2]), "+f"(c[3])
                 : "r"(a[0]), "r"(a[1]), "r"(a[2]), "r"(a[3]), "r"(b0), "r"(b1));
}
__device__ __forceinline__ void mbar_init(uint32_t mbar, uint32_t cnt) {
    asm volatile("mbarrier.init.shared.b64 [%0], %1;" :: "r"(mbar), "r"(cnt) : "memory");
}
__device__ __forceinline__ void mbar_expect_tx(uint32_t mbar, uint32_t bytes) {
    asm volatile("mbarrier.arrive.expect_tx.shared.b64 _, [%0], %1;"
                 :: "r"(mbar), "r"(bytes) : "memory");
}
__device__ __forceinline__ void mbar_wait(uint32_t mbar, uint32_t parity) {
    asm volatile(
        "{\n\t.reg .pred P1;\n\t"
        "WL_%=:\n\t"
        "mbarrier.try_wait.parity.acquire.cta.shared::cta.b64 P1, [%0], %1, 0x989680;\n\t"
        "@P1 bra.uni WD_%=;\n\t"
        "bra.uni WL_%=;\n\t"
        "WD_%=:\n\t}"
        :: "r"(mbar), "r"(parity) : "memory");
}
// bulk TMA g->s with L2 evict_last cache hint: keep weights L2-resident across steps
__device__ __forceinline__ void bulk_g2s_ll(uint32_t dst, const void* src, uint32_t bytes,
                                            uint32_t mbar, uint64_t pol) {
    asm volatile("cp.async.bulk.shared::cluster.global.mbarrier::complete_tx::bytes"
                 ".L2::cache_hint [%0], [%1], %2, [%3], %4;"
                 :: "r"(dst), "l"(src), "r"(bytes), "r"(mbar), "l"(pol) : "memory");
}
__device__ __forceinline__ uint64_t mk_policy_evict_last() {
    uint64_t pol;
    asm("createpolicy.fractional.L2::evict_last.b64 %0, 1.0;" : "=l"(pol));
    return pol;
}

// ---------------- prep: tiled, swizzled, augmented, gate-interleaved weights ----------------
__global__ void prep_weights(const float* __restrict__ encW, const float* __restrict__ decW) {
    size_t idx = (size_t)blockIdx.x * blockDim.x + threadIdx.x;
    const size_t one = (size_t)N3 * KK;
    if (idx >= 2 * one) return;
    int which = idx >= one;
    size_t rem = which ? idx - one : idx;
    int j = (int)(rem / KK);
    int k = (int)(rem % KK);
    int u = j / 3, g = j - 3 * u;
    const float* W = which ? decW : encW;
    float w = W[(size_t)(g * HH + u) * HH + (k & 1023)];
    __nv_bfloat16 hi = __float2bfloat16(w);
    __nv_bfloat16 out = (k < 2048) ? hi : __float2bfloat16(w - __bfloat162float(hi));
    int nb = j / 96, jr = j - nb * 96;
    int c = k >> 6, kk = k & 63;
    uint32_t swb = sw128((uint32_t)(jr * 128 + kk * 2));
    g_Wt[which][nb][c][swb >> 1] = out;
}

// ---------------- prep: biases, permuted W_ih, zero h tiles, init d_out = fc_b ----------------
__global__ void prep_misc(const float* __restrict__ ebih, const float* __restrict__ ebhh,
                          const float* __restrict__ dbih, const float* __restrict__ dbhh,
                          const float* __restrict__ eWih, const float* __restrict__ dWih,
                          const float* __restrict__ fcb, float* __restrict__ dout) {
    int tid = blockIdx.x * blockDim.x + threadIdx.x;
    int stride = gridDim.x * blockDim.x;
    for (int i = tid; i < N3; i += stride) {
        int u = i / 3, g = i - 3 * u;
        int o = g * HH + u;
        g_bih_e[i] = ebih[o];
        g_bhh_e[i] = ebhh[o];
        g_bih_d[i] = dbih[o];
        g_bhh_d[i] = dbhh[o];
        g_Wih_d[i] = dWih[o];
    }
    for (int i = tid; i < HH * 192; i += stride) {
        int u = i / 192, rem = i - u * 192;
        int g = rem >> 6, f = rem & 63;
        g_Wihp_e[i] = eWih[(size_t)(g * HH + u) * FF + f];
    }
    const int nh = 2 * 4 * NC * 64 * 64 / 2;    // u32 words over both h buffers
    for (int i = tid; i < nh; i += stride) ((uint32_t*)g_ht)[i] = 0u;
    for (int i = tid; i < BB * TLEN; i += stride) dout[i] = fcb[0];
}

// ---------------- one recurrent step: bulk-fed GEMM (bf16x3) + fused GRU epilogue ----------------
// grid (32, 4): blockIdx.x = 96-col tile, blockIdx.y = 64-row batch tile. 256 threads.
__global__ __launch_bounds__(256) void gru_step_kernel(
    int t, int mode, int par,
    const float* __restrict__ x, const float* __restrict__ fcW, float* __restrict__ dout)
{
    const float* __restrict__ bih = mode ? g_bih_d : g_bih_e;
    const float* __restrict__ bhh = mode ? g_bhh_d : g_bhh_e;

    extern __shared__ __align__(16) unsigned char smem_raw[];
    const int tid = threadIdx.x;
    const int lane = tid & 31, warp = tid >> 5;
    const int wm = warp >> 2, wn = warp & 3;     // 2 x 4 warps -> 32x24 warp tiles
    const int nb = blockIdx.x, mb = blockIdx.y;

    const uint32_t smBase = (uint32_t)__cvta_generic_to_shared(smem_raw);
    const uint32_t mbar0 = smBase;               // 8 mbarriers x 8B in header
    const uint32_t smData = smBase + HDR;

    const __nv_bfloat16* __restrict__ Asrc = &g_ht[par][mb][0][0];
    const __nv_bfloat16* __restrict__ Bsrc = &g_Wt[mode][nb][0][0];
    __nv_bfloat16* __restrict__ hdst = &g_ht[par ^ 1][mb][0][0];
    const __nv_bfloat16* __restrict__ hsrc = Asrc;

    if (tid == 0) {
        #pragma unroll
        for (int s = 0; s < NSTG; s++) mbar_init(mbar0 + 8 * s, 1);
    }
    __syncthreads();

    const uint64_t pol = mk_policy_evict_last();

    auto issue = [&](int c) {
        const int s = c & (NSTG - 1);
        const uint32_t mb_ = mbar0 + 8 * s;
        mbar_expect_tx(mb_, STAGE_B);
        const uint32_t d = smData + s * STAGE_B;
        bulk_g2s_ll(d,            Asrc + (size_t)c * 4096, A_TILE_B, mb_, pol);
        bulk_g2s_ll(d + A_TILE_B, Bsrc + (size_t)c * 6144, B_TILE_B, mb_, pol);
    };

    if (tid == 0) {
        #pragma unroll
        for (int s = 0; s < NSTG - 1; s++) issue(s);
    }

    float acc[2][3][4];
    #pragma unroll
    for (int mi = 0; mi < 2; mi++)
        #pragma unroll
        for (int ni = 0; ni < 3; ni++)
            #pragma unroll
            for (int q = 0; q < 4; q++) acc[mi][ni][q] = 0.f;

    for (int c = 0; c < NC; c++) {
        __syncthreads();                          // previous stage slot now free
        if (tid == 0 && c + NSTG - 1 < NC) issue(c + NSTG - 1);
        mbar_wait(mbar0 + 8 * (c & (NSTG - 1)), (c >> 3) & 1);

        const uint32_t sA = smData + (c & (NSTG - 1)) * STAGE_B;
        const uint32_t sB = sA + A_TILE_B;
        #pragma unroll
        for (int ks = 0; ks < 4; ks++) {
            uint32_t ra[2][4], rb[3][2];
            #pragma unroll
            for (int mi = 0; mi < 2; mi++) {
                uint32_t off = (uint32_t)((wm * 32 + mi * 16 + (lane & 15)) * 128
                                          + ks * 32 + (lane >> 4) * 16);
                ldsm_x4(ra[mi], sA + sw128(off));
            }
            #pragma unroll
            for (int ni = 0; ni < 3; ni++) {
                uint32_t off = (uint32_t)((wn * 24 + ni * 8 + (lane & 7)) * 128
                                          + ks * 32 + ((lane >> 3) & 1) * 16);
                ldsm_x2(rb[ni], sB + sw128(off));
            }
            #pragma unroll
            for (int mi = 0; mi < 2; mi++)
                #pragma unroll
                for (int ni = 0; ni < 3; ni++)
                    mma_bf16(acc[mi][ni], ra[mi], rb[ni][0], rb[ni][1]);
        }
    }

    // ---- stage accumulators to smem (reuse data region) ----
    __syncthreads();
    float* Csm = (float*)(smem_raw + HDR);               // 64 x 96, pitch 99
    float* Xs  = (float*)(smem_raw + HDR + 25600);       // 64 x 64 floats
    #pragma unroll
    for (int mi = 0; mi < 2; mi++)
        #pragma unroll
        for (int ni = 0; ni < 3; ni++) {
            int m = wm * 32 + mi * 16 + (lane >> 2);
            int n = wn * 24 + ni * 8 + ((lane & 3) << 1);
            Csm[m * 99 + n]           = acc[mi][ni][0];
            Csm[m * 99 + n + 1]       = acc[mi][ni][1];
            Csm[(m + 8) * 99 + n]     = acc[mi][ni][2];
            Csm[(m + 8) * 99 + n + 1] = acc[mi][ni][3];
        }
    if (mode == 0) {
        #pragma unroll
        for (int q = 0; q < 4; q++) {
            int id = tid + q * 256;
            int r = id >> 4, c4 = id & 15;
            ((float4*)Xs)[r * 16 + c4] =
                *(const float4*)(x + ((size_t)(mb * 64 + r) * TT + t) * FF + c4 * 4);
        }
    }
    __syncthreads();

    // ---- fused GRU epilogue: each thread owns (batch row bl, 8 hidden units) ----
    const int bl = tid >> 2, uq = tid & 3;
    const int b = mb * 64 + bl;
    float inp = 0.f;
    if (mode && t > 0) inp = dout[b * TLEN + (t - 1)];
    float fcsum = 0.f;
    const float4* xs4 = (const float4*)(Xs + bl * 64);

    #pragma unroll
    for (int i = 0; i < 8; i++) {
        int ul = uq * 8 + i;
        int u = nb * 32 + ul;
        float ar = Csm[bl * 99 + ul * 3 + 0];
        float az = Csm[bl * 99 + ul * 3 + 1];
        float an = Csm[bl * 99 + ul * 3 + 2];
        float gr, gz, gn;
        if (mode == 0) {
            gr = gz = gn = 0.f;
            const float4* wr4 = (const float4*)(g_Wihp_e + (size_t)u * 192);
            #pragma unroll
            for (int q = 0; q < 16; q++) {
                float4 xv = xs4[q];
                float4 a = wr4[q], bq = wr4[16 + q], cq = wr4[32 + q];
                gr += xv.x * a.x + xv.y * a.y + xv.z * a.z + xv.w * a.w;
                gz += xv.x * bq.x + xv.y * bq.y + xv.z * bq.z + xv.w * bq.w;
                gn += xv.x * cq.x + xv.y * cq.y + xv.z * cq.z + xv.w * cq.w;
            }
        } else {
            gr = inp * g_Wih_d[u * 3 + 0];
            gz = inp * g_Wih_d[u * 3 + 1];
            gn = inp * g_Wih_d[u * 3 + 2];
        }
        // hprev = h_hi (chunk u>>6) + h_lo (chunk 16 + u>>6), swizzled tile layout
        const int kk2 = (u & 63) * 2;
        const uint32_t swo = sw128((uint32_t)(bl * 128 + kk2));
        float hp_hi = __bfloat162float(
            *(const __nv_bfloat16*)((const char*)hsrc + (size_t)(u >> 6) * A_TILE_B + swo));
        float hp_lo = __bfloat162float(
            *(const __nv_bfloat16*)((const char*)hsrc + (size_t)(16 + (u >> 6)) * A_TILE_B + swo));
        float hprev = hp_hi + hp_lo;
        float rg = 1.f / (1.f + __expf(-(gr + bih[u * 3 + 0] + ar + bhh[u * 3 + 0])));
        float zg = 1.f / (1.f + __expf(-(gz + bih[u * 3 + 1] + az + bhh[u * 3 + 1])));
        float ng = tanhf(gn + bih[u * 3 + 2] + rg * (an + bhh[u * 3 + 2]));
        float hn = (1.f - zg) * ng + zg * hprev;
        __nv_bfloat16 hi = __float2bfloat16(hn);
        __nv_bfloat16 lo = __float2bfloat16(hn - __bfloat162float(hi));
        *(__nv_bfloat16*)((char*)hdst + (size_t)(u >> 6) * A_TILE_B + swo)        = hi;
        *(__nv_bfloat16*)((char*)hdst + (size_t)(32 + (u >> 6)) * A_TILE_B + swo) = hi;
        *(__nv_bfloat16*)((char*)hdst + (size_t)(16 + (u >> 6)) * A_TILE_B + swo) = lo;
        if (mode) fcsum += hn * fcW[u];
    }
    if (mode) {
        fcsum += __shfl_down_sync(0xffffffffu, fcsum, 2, 4);
        fcsum += __shfl_down_sync(0xffffffffu, fcsum, 1, 4);
        if (uq == 0) atomicAdd(&dout[b * TLEN + t], fcsum);
    }
}

// ---------------- host launch ----------------
extern "C" void kernel_launch(void* const* d_in, const int* in_sizes, int n_in,
                              void* d_out, int out_size) {
    const float* x    = (const float*)d_in[0];
    const float* eWih = (const float*)d_in[1];
    const float* eWhh = (const float*)d_in[2];
    const float* ebih = (const float*)d_in[3];
    const float* ebhh = (const float*)d_in[4];
    const float* dWih = (const float*)d_in[5];
    const float* dWhh = (const float*)d_in[6];
    const float* dbih = (const float*)d_in[7];
    const float* dbhh = (const float*)d_in[8];
    const float* fcW  = (const float*)d_in[9];
    const float* fcb  = (const float*)d_in[10];
    float* out = (float*)d_out;

    cudaFuncSetAttribute(gru_step_kernel,
                         cudaFuncAttributeMaxDynamicSharedMemorySize, SMEMSZ);

    prep_weights<<<(unsigned)((2 * (size_t)N3 * KK + 255) / 256), 256>>>(eWhh, dWhh);
    prep_misc<<<1024, 256>>>(ebih, ebhh, dbih, dbhh, eWih, dWih, fcb, out);

    dim3 grid(N3 / 96, BB / 64);   // (32, 4)
    for (int t = 0; t < TT; t++)
        gru_step_kernel<<<grid, 256, SMEMSZ>>>(t, 0, t & 1, x, fcW, out);
    for (int s = 0; s < TLEN; s++)
        gru_step_kernel<<<grid, 256, SMEMSZ>>>(s, 1, s & 1, x, fcW, out);
}

// round 13
// speedup vs baseline: 4.0916x; 1.2256x over previous
#include <cuda_runtime.h>
#include <cuda_bf16.h>
#include <cstdint>

#define BB 256   // batch
#define TT 512   // encoder steps
#define FF 64    // input features
#define HH 1024  // hidden
#define TLEN 64  // decoder steps
#define N3 3072  // 3*H output columns (gate-interleaved)
#define KK 3072  // augmented K: [h_hi | h_lo | h_hi]
#define NC 48    // K chunks of 64
#define NSTG 4   // pipeline stages (power of 2)

#define A_TILE_B 8192           // h tile: 64 rows x 128B (SW128)
#define B_TILE_B 6144           // W tile: 48 rows x 128B
#define STAGE_B  (A_TILE_B + B_TILE_B)   // 14336
#define HDR 1024
#define SMEMSZ (HDR + NSTG * STAGE_B)    // 58368  -> 2 CTAs/SM

__device__ __forceinline__ uint32_t sw128(uint32_t off) { return off ^ ((off >> 3) & 0x70); }

// ---------------- device scratch (static globals; no allocation) ----------------
// Weights as contiguous pre-swizzled tiles: [2][64 nb][48 c][48*64]
__device__ __align__(128) __nv_bfloat16 g_Wt[2][64][NC][48 * 64];
// h as contiguous pre-swizzled tiles: [2 par][4 mb][48 c][64*64]  (unchanged layout)
__device__ __align__(128) __nv_bfloat16 g_ht[2][4][NC][64 * 64];
__device__ float g_bih_e[N3], g_bhh_e[N3], g_bih_d[N3], g_bhh_d[N3]; // permuted biases
__device__ float g_Wihp_e[(size_t)HH * 192];            // enc W_ih, per-unit [r|z|n]
__device__ float g_Wih_d[N3];                           // dec W_ih (scalar input), permuted

// ---------------- PTX helpers ----------------
__device__ __forceinline__ void ldsm_x4(uint32_t* r, uint32_t addr) {
    asm volatile("ldmatrix.sync.aligned.m8n8.x4.shared.b16 {%0,%1,%2,%3}, [%4];"
                 : "=r"(r[0]), "=r"(r[1]), "=r"(r[2]), "=r"(r[3]) : "r"(addr));
}
__device__ __forceinline__ void ldsm_x2(uint32_t* r, uint32_t addr) {
    asm volatile("ldmatrix.sync.aligned.m8n8.x2.shared.b16 {%0,%1}, [%2];"
                 : "=r"(r[0]), "=r"(r[1]) : "r"(addr));
}
__device__ __forceinline__ void mma_bf16(float* c, const uint32_t* a, uint32_t b0, uint32_t b1) {
    asm volatile("mma.sync.aligned.m16n8k16.row.col.f32.bf16.bf16.f32 "
                 "{%0,%1,%2,%3}, {%4,%5,%6,%7}, {%8,%9}, {%0,%1,%2,%3};"
                 : "+f"(c[0]), "+f"(c[1]), "+f"(c[2]), "+f"(c[3])
                 : "r"(a[0]), "r"(a[1]), "r"(a[2]), "r"(a[3]), "r"(b0), "r"(b1));
}
__device__ __forceinline__ void mbar_init(uint32_t mbar, uint32_t cnt) {
    asm volatile("mbarrier.init.shared.b64 [%0], %1;" :: "r"(mbar), "r"(cnt) : "memory");
}
__device__ __forceinline__ void mbar_expect_tx(uint32_t mbar, uint32_t bytes) {
    asm volatile("mbarrier.arrive.expect_tx.shared.b64 _, [%0], %1;"
                 :: "r"(mbar), "r"(bytes) : "memory");
}
__device__ __forceinline__ void mbar_wait(uint32_t mbar, uint32_t parity) {
    asm volatile(
        "{\n\t.reg .pred P1;\n\t"
        "WL_%=:\n\t"
        "mbarrier.try_wait.parity.acquire.cta.shared::cta.b64 P1, [%0], %1, 0x989680;\n\t"
        "@P1 bra.uni WD_%=;\n\t"
        "bra.uni WL_%=;\n\t"
        "WD_%=:\n\t}"
        :: "r"(mbar), "r"(parity) : "memory");
}
__device__ __forceinline__ void bulk_g2s(uint32_t dst, const void* src, uint32_t bytes, uint32_t mbar) {
    asm volatile("cp.async.bulk.shared::cluster.global.mbarrier::complete_tx::bytes "
                 "[%0], [%1], %2, [%3];"
                 :: "r"(dst), "l"(src), "r"(bytes), "r"(mbar) : "memory");
}

// ---------------- prep: tiled, swizzled, augmented, gate-interleaved weights ----------------
__global__ void prep_weights(const float* __restrict__ encW, const float* __restrict__ decW) {
    size_t idx = (size_t)blockIdx.x * blockDim.x + threadIdx.x;
    const size_t one = (size_t)N3 * KK;
    if (idx >= 2 * one) return;
    int which = idx >= one;
    size_t rem = which ? idx - one : idx;
    int j = (int)(rem / KK);
    int k = (int)(rem % KK);
    int u = j / 3, g = j - 3 * u;
    const float* W = which ? decW : encW;
    float w = W[(size_t)(g * HH + u) * HH + (k & 1023)];
    __nv_bfloat16 hi = __float2bfloat16(w);
    __nv_bfloat16 out = (k < 2048) ? hi : __float2bfloat16(w - __bfloat162float(hi));
    int nb = j / 48, jr = j - nb * 48;
    int c = k >> 6, kk = k & 63;
    uint32_t swb = sw128((uint32_t)(jr * 128 + kk * 2));
    g_Wt[which][nb][c][swb >> 1] = out;
}

// ---------------- prep: biases, permuted W_ih, zero h tiles, init d_out = fc_b ----------------
__global__ void prep_misc(const float* __restrict__ ebih, const float* __restrict__ ebhh,
                          const float* __restrict__ dbih, const float* __restrict__ dbhh,
                          const float* __restrict__ eWih, const float* __restrict__ dWih,
                          const float* __restrict__ fcb, float* __restrict__ dout) {
    int tid = blockIdx.x * blockDim.x + threadIdx.x;
    int stride = gridDim.x * blockDim.x;
    for (int i = tid; i < N3; i += stride) {
        int u = i / 3, g = i - 3 * u;
        int o = g * HH + u;
        g_bih_e[i] = ebih[o];
        g_bhh_e[i] = ebhh[o];
        g_bih_d[i] = dbih[o];
        g_bhh_d[i] = dbhh[o];
        g_Wih_d[i] = dWih[o];
    }
    for (int i = tid; i < HH * 192; i += stride) {
        int u = i / 192, rem = i - u * 192;
        int g = rem >> 6, f = rem & 63;
        g_Wihp_e[i] = eWih[(size_t)(g * HH + u) * FF + f];
    }
    const int nh = 2 * 4 * NC * 64 * 64 / 2;    // u32 words over both h buffers
    for (int i = tid; i < nh; i += stride) ((uint32_t*)g_ht)[i] = 0u;
    for (int i = tid; i < BB * TLEN; i += stride) dout[i] = fcb[0];
}

// ---------------- one recurrent step: 2-CTA/SM bulk-fed GEMM + fused GRU epilogue ----------------
// grid (64, 4): blockIdx.x = 48-col tile (16 units), blockIdx.y = 64-row batch tile.
// 128 threads, 4 warps as 2(M) x 2(N), warp tile 32x24.
__global__ __launch_bounds__(128, 2) void gru_step_kernel(
    int t, int mode, int par,
    const float* __restrict__ x, const float* __restrict__ fcW, float* __restrict__ dout)
{
    const float* __restrict__ bih = mode ? g_bih_d : g_bih_e;
    const float* __restrict__ bhh = mode ? g_bhh_d : g_bhh_e;

    extern __shared__ __align__(16) unsigned char smem_raw[];
    const int tid = threadIdx.x;
    const int lane = tid & 31, warp = tid >> 5;
    const int wm = warp >> 1, wn = warp & 1;     // 2 x 2 warps -> 32x24 warp tiles
    const int nb = blockIdx.x, mb = blockIdx.y;

    const uint32_t smBase = (uint32_t)__cvta_generic_to_shared(smem_raw);
    const uint32_t mbar0 = smBase;               // 4 mbarriers x 8B in header
    const uint32_t smData = smBase + HDR;

    const __nv_bfloat16* __restrict__ Asrc = &g_ht[par][mb][0][0];
    const __nv_bfloat16* __restrict__ Bsrc = &g_Wt[mode][nb][0][0];
    __nv_bfloat16* __restrict__ hdst = &g_ht[par ^ 1][mb][0][0];
    const __nv_bfloat16* __restrict__ hsrc = Asrc;

    if (tid == 0) {
        #pragma unroll
        for (int s = 0; s < NSTG; s++) mbar_init(mbar0 + 8 * s, 1);
    }
    __syncthreads();

    auto issue = [&](int c) {
        const int s = c & (NSTG - 1);
        const uint32_t mb_ = mbar0 + 8 * s;
        mbar_expect_tx(mb_, STAGE_B);
        const uint32_t d = smData + s * STAGE_B;
        bulk_g2s(d,            Asrc + (size_t)c * 4096, A_TILE_B, mb_);
        bulk_g2s(d + A_TILE_B, Bsrc + (size_t)c * 3072, B_TILE_B, mb_);
    };

    if (tid == 0) {
        #pragma unroll
        for (int s = 0; s < NSTG - 1; s++) issue(s);
    }

    float acc[2][3][4];
    #pragma unroll
    for (int mi = 0; mi < 2; mi++)
        #pragma unroll
        for (int ni = 0; ni < 3; ni++)
            #pragma unroll
            for (int q = 0; q < 4; q++) acc[mi][ni][q] = 0.f;

    for (int c = 0; c < NC; c++) {
        __syncthreads();                          // previous stage slot drained by all warps
        if (tid == 0 && c + NSTG - 1 < NC) issue(c + NSTG - 1);
        mbar_wait(mbar0 + 8 * (c & (NSTG - 1)), (c >> 2) & 1);

        const uint32_t sA = smData + (c & (NSTG - 1)) * STAGE_B;
        const uint32_t sB = sA + A_TILE_B;
        #pragma unroll
        for (int ks = 0; ks < 4; ks++) {
            uint32_t ra[2][4], rb4[4], rb2[2];
            #pragma unroll
            for (int mi = 0; mi < 2; mi++) {
                uint32_t off = (uint32_t)((wm * 32 + mi * 16 + (lane & 15)) * 128
                                          + ks * 32 + (lane >> 4) * 16);
                ldsm_x4(ra[mi], sA + sw128(off));
            }
            {   // B n16k16 via one x4 (rows wn*24 .. +15)
                uint32_t off = (uint32_t)((wn * 24 + (lane & 15)) * 128
                                          + ks * 32 + (lane >> 4) * 16);
                ldsm_x4(rb4, sB + sw128(off));
            }
            {   // B n8k16 via x2 (rows wn*24+16 .. +23)
                uint32_t off = (uint32_t)((wn * 24 + 16 + (lane & 7)) * 128
                                          + ks * 32 + ((lane >> 3) & 1) * 16);
                ldsm_x2(rb2, sB + sw128(off));
            }
            // x4 B reg order: {n0-7 k0-7, n8-15 k0-7, n0-7 k8-15, n8-15 k8-15}
            #pragma unroll
            for (int mi = 0; mi < 2; mi++) {
                mma_bf16(acc[mi][0], ra[mi], rb4[0], rb4[2]);
                mma_bf16(acc[mi][1], ra[mi], rb4[1], rb4[3]);
                mma_bf16(acc[mi][2], ra[mi], rb2[0], rb2[1]);
            }
        }
    }

    // ---- stage accumulators to smem (reuse data region) ----
    __syncthreads();
    float* Csm = (float*)(smem_raw + HDR);               // 64 x 48, pitch 51 (13056 B)
    float* Xs  = (float*)(smem_raw + HDR + 13312);       // 64 x 64 floats (16384 B)
    #pragma unroll
    for (int mi = 0; mi < 2; mi++)
        #pragma unroll
        for (int ni = 0; ni < 3; ni++) {
            int m = wm * 32 + mi * 16 + (lane >> 2);
            int n = wn * 24 + ni * 8 + ((lane & 3) << 1);
            Csm[m * 51 + n]           = acc[mi][ni][0];
            Csm[m * 51 + n + 1]       = acc[mi][ni][1];
            Csm[(m + 8) * 51 + n]     = acc[mi][ni][2];
            Csm[(m + 8) * 51 + n + 1] = acc[mi][ni][3];
        }
    if (mode == 0) {
        #pragma unroll
        for (int q = 0; q < 8; q++) {
            int id = tid + q * 128;
            int r = id >> 4, c4 = id & 15;
            ((float4*)Xs)[r * 16 + c4] =
                *(const float4*)(x + ((size_t)(mb * 64 + r) * TT + t) * FF + c4 * 4);
        }
    }
    __syncthreads();

    // ---- fused GRU epilogue: each thread owns (batch row bl, 8 hidden units) ----
    const int bl = tid >> 1, uq = tid & 1;
    const int b = mb * 64 + bl;
    float inp = 0.f;
    if (mode && t > 0) inp = dout[b * TLEN + (t - 1)];
    float fcsum = 0.f;
    const float4* xs4 = (const float4*)(Xs + bl * 64);

    #pragma unroll
    for (int i = 0; i < 8; i++) {
        int ul = uq * 8 + i;
        int u = nb * 16 + ul;
        float ar = Csm[bl * 51 + ul * 3 + 0];
        float az = Csm[bl * 51 + ul * 3 + 1];
        float an = Csm[bl * 51 + ul * 3 + 2];
        float gr, gz, gn;
        if (mode == 0) {
            gr = gz = gn = 0.f;
            const float4* wr4 = (const float4*)(g_Wihp_e + (size_t)u * 192);
            #pragma unroll
            for (int q = 0; q < 16; q++) {
                float4 xv = xs4[q];
                float4 a = wr4[q], bq = wr4[16 + q], cq = wr4[32 + q];
                gr += xv.x * a.x + xv.y * a.y + xv.z * a.z + xv.w * a.w;
                gz += xv.x * bq.x + xv.y * bq.y + xv.z * bq.z + xv.w * bq.w;
                gn += xv.x * cq.x + xv.y * cq.y + xv.z * cq.z + xv.w * cq.w;
            }
        } else {
            gr = inp * g_Wih_d[u * 3 + 0];
            gz = inp * g_Wih_d[u * 3 + 1];
            gn = inp * g_Wih_d[u * 3 + 2];
        }
        // hprev = h_hi (chunk u>>6) + h_lo (chunk 16 + u>>6), swizzled tile layout
        const int kk2 = (u & 63) * 2;
        const uint32_t swo = sw128((uint32_t)(bl * 128 + kk2));
        float hp_hi = __bfloat162float(
            *(const __nv_bfloat16*)((const char*)hsrc + (size_t)(u >> 6) * A_TILE_B + swo));
        float hp_lo = __bfloat162float(
            *(const __nv_bfloat16*)((const char*)hsrc + (size_t)(16 + (u >> 6)) * A_TILE_B + swo));
        float hprev = hp_hi + hp_lo;
        float rg = 1.f / (1.f + __expf(-(gr + bih[u * 3 + 0] + ar + bhh[u * 3 + 0])));
        float zg = 1.f / (1.f + __expf(-(gz + bih[u * 3 + 1] + az + bhh[u * 3 + 1])));
        float ng = tanhf(gn + bih[u * 3 + 2] + rg * (an + bhh[u * 3 + 2]));
        float hn = (1.f - zg) * ng + zg * hprev;
        __nv_bfloat16 hi = __float2bfloat16(hn);
        __nv_bfloat16 lo = __float2bfloat16(hn - __bfloat162float(hi));
        *(__nv_bfloat16*)((char*)hdst + (size_t)(u >> 6) * A_TILE_B + swo)        = hi;
        *(__nv_bfloat16*)((char*)hdst + (size_t)(32 + (u >> 6)) * A_TILE_B + swo) = hi;
        *(__nv_bfloat16*)((char*)hdst + (size_t)(16 + (u >> 6)) * A_TILE_B + swo) = lo;
        if (mode) fcsum += hn * fcW[u];
    }
    if (mode) {
        fcsum += __shfl_down_sync(0xffffffffu, fcsum, 1, 2);
        if (uq == 0) atomicAdd(&dout[b * TLEN + t], fcsum);
    }
}

// ---------------- host launch ----------------
extern "C" void kernel_launch(void* const* d_in, const int* in_sizes, int n_in,
                              void* d_out, int out_size) {
    const float* x    = (const float*)d_in[0];
    const float* eWih = (const float*)d_in[1];
    const float* eWhh = (const float*)d_in[2];
    const float* ebih = (const float*)d_in[3];
    const float* ebhh = (const float*)d_in[4];
    const float* dWih = (const float*)d_in[5];
    const float* dWhh = (const float*)d_in[6];
    const float* dbih = (const float*)d_in[7];
    const float* dbhh = (const float*)d_in[8];
    const float* fcW  = (const float*)d_in[9];
    const float* fcb  = (const float*)d_in[10];
    float* out = (float*)d_out;

    cudaFuncSetAttribute(gru_step_kernel,
                         cudaFuncAttributeMaxDynamicSharedMemorySize, SMEMSZ);

    prep_weights<<<(unsigned)((2 * (size_t)N3 * KK + 255) / 256), 256>>>(eWhh, dWhh);
    prep_misc<<<1024, 256>>>(ebih, ebhh, dbih, dbhh, eWih, dWih, fcb, out);

    dim3 grid(N3 / 48, BB / 64);   // (64, 4) = 256 CTAs -> 2 per SM
    for (int t = 0; t < TT; t++)
        gru_step_kernel<<<grid, 128, SMEMSZ>>>(t, 0, t & 1, x, fcW, out);
    for (int s = 0; s < TLEN; s++)
        gru_step_kernel<<<grid, 128, SMEMSZ>>>(s, 1, s & 1, x, fcW, out);
}